// round 6
// baseline (speedup 1.0000x reference)
#include <cuda_runtime.h>
#include <cstdint>

// ---------------------------------------------------------------------------
// Model_57183194578962 — fused neighbor-attention + cosine loss
// B=512, N=100, E=512, D_MODEL=1024, H=8, DEPTH=128, VOCAB=50000
//
// Round 4: double-buffered 64x128 SGEMM engine (full-chip grids),
//          U halved via rank-4 fold of u_bot, att epilogue split out.
// ---------------------------------------------------------------------------

#define Bsz 512
#define Nn  100
#define Ee  512
#define DM  1024
#define Hh  8
#define DEPTH 128

// ------------------------- static scratch ----------------------------------
__device__ float g_Xq[2 * Bsz * DM];         // x rows 0,1 per batch   [1024,1024]
__device__ float g_Q [2 * Bsz * DM];         // Q rows                 [1024,1024]
__device__ float g_U [16 * Bsz * Ee];        // u_top  [(bq)*8+h][512]
__device__ float g_r4[16 * Bsz * 4];         // pos_W @ u_bot per bqh
__device__ float g_c0[16 * Bsz];             // (pos_b@Wk_bot + bk)·q_h
__device__ float g_xbar[16 * Bsz * Ee];      // Σ w_n t_n  [(bq)*8+h][512]
__device__ float g_wpos[16 * Bsz * 4];       // Σ w_n pos_n
__device__ float g_att[2 * Bsz * DM];        // attention output       [1024,1024]
__device__ float g_O [2 * Bsz * DM];         // att @ Wo + bo
__device__ float g_pool[Bsz * DM];
__device__ float g_enc[Bsz * Ee];
__device__ float g_Mv[4 * DM], g_cv[DM];
__device__ float g_Mc[4 * Ee], g_cc[Ee];
__device__ float g_Rk[4 * DM], g_s1[DM];     // pos_W@Wk_bot, pos_b@Wk_bot+bk

// ---------------------------------------------------------------------------
// Tiny fused matmuls: M_out[c][n] = sum_k W4[c][k]*Wbot[k][n],
//                     c_out[n]   = sum_k b_in[k]*Wbot[k][n] + b_out[n]
// ---------------------------------------------------------------------------
__global__ void fuse_small(const float* __restrict__ W4, const float* __restrict__ b_in,
                           const float* __restrict__ Wbot, const float* __restrict__ b_out,
                           float* __restrict__ M_out, float* __restrict__ c_out,
                           int K2, int Nout, int ldb) {
    int n = blockIdx.x * blockDim.x + threadIdx.x;
    if (n >= Nout) return;
    float m0 = 0.f, m1 = 0.f, m2 = 0.f, m3 = 0.f, c = 0.f;
    for (int k = 0; k < K2; k++) {
        float w = Wbot[(size_t)k * ldb + n];
        m0 += W4[k] * w;
        m1 += W4[K2 + k] * w;
        m2 += W4[2 * K2 + k] * w;
        m3 += W4[3 * K2 + k] * w;
        c  += b_in[k] * w;
    }
    M_out[n] = m0; M_out[Nout + n] = m1;
    M_out[2 * Nout + n] = m2; M_out[3 * Nout + n] = m3;
    c_out[n] = c + b_out[n];
}

// ---------------------------------------------------------------------------
__global__ void build_xq(const int* __restrict__ nt, const float* __restrict__ npos,
                         const float* __restrict__ text_table,
                         const float* __restrict__ pos_W, const float* __restrict__ pos_b,
                         float* __restrict__ Xq) {
    int r = blockIdx.x;               // 0..1023 = b*2 + i
    int b = r >> 1, i = r & 1;
    int id = nt[b * Nn + i];
    const float* trow = text_table + (size_t)id * Ee;
    const float* pp = npos + (size_t)(b * Nn + i) * 4;
    float p0 = pp[0], p1 = pp[1], p2 = pp[2], p3 = pp[3];
    float* xr = Xq + (size_t)r * DM;
    for (int j = threadIdx.x; j < Ee; j += blockDim.x) {
        xr[j] = trow[j];
        xr[Ee + j] = p0 * pos_W[j] + p1 * pos_W[Ee + j] + p2 * pos_W[2 * Ee + j]
                   + p3 * pos_W[3 * Ee + j] + pos_b[j];
    }
}

// ---------------------------------------------------------------------------
// Double-buffered SGEMM: C = A @ B (+bias). Tile 64(M) x 128(N) x 16(K).
// 256 threads, 4x8 per-thread tile, register prefetch. All dims must be
// multiples of the tile. gridDim.z batches via pointer offsets.
// ---------------------------------------------------------------------------
__global__ void __launch_bounds__(256) dbgemm(
        const float* __restrict__ A0, int lda, long azoff,
        const float* __restrict__ B0, int ldb, long bzoff,
        float* __restrict__ C0, int ldc, long czoff,
        const float* __restrict__ bias, int K) {
    const float* A = A0 + (size_t)blockIdx.z * azoff;
    const float* B = B0 + (size_t)blockIdx.z * bzoff;
    float*       C = C0 + (size_t)blockIdx.z * czoff;
    __shared__ float As[2][16][64];
    __shared__ float Bs[2][16][128];
    int tid = threadIdx.x;
    int row0 = blockIdx.y * 64, col0 = blockIdx.x * 128;
    int tx = tid & 15, ty = tid >> 4;
    int ar = tid >> 2, ac = (tid & 3) << 2;
    int br0 = tid >> 5, bc0 = (tid & 31) << 2;        // rows 0..7
    int br1 = br0 + 8;                                // rows 8..15
    float acc[4][8] = {};
    float4 pa, pb0, pb1;

    // prologue: tile 0
    pa  = *(const float4*)(A + (size_t)(row0 + ar) * lda + ac);
    pb0 = *(const float4*)(B + (size_t)br0 * ldb + col0 + bc0);
    pb1 = *(const float4*)(B + (size_t)br1 * ldb + col0 + bc0);
    As[0][ac + 0][ar] = pa.x; As[0][ac + 1][ar] = pa.y;
    As[0][ac + 2][ar] = pa.z; As[0][ac + 3][ar] = pa.w;
    *(float4*)&Bs[0][br0][bc0] = pb0;
    *(float4*)&Bs[0][br1][bc0] = pb1;
    __syncthreads();

    int nk = K >> 4;
    for (int k0 = 0; k0 < nk; k0++) {
        int cur = k0 & 1;
        if (k0 + 1 < nk) {
            int kb = (k0 + 1) << 4;
            pa  = *(const float4*)(A + (size_t)(row0 + ar) * lda + kb + ac);
            pb0 = *(const float4*)(B + (size_t)(kb + br0) * ldb + col0 + bc0);
            pb1 = *(const float4*)(B + (size_t)(kb + br1) * ldb + col0 + bc0);
        }
        #pragma unroll
        for (int kk = 0; kk < 16; kk++) {
            float a[4], b[8];
            *(float4*)a      = *(const float4*)&As[cur][kk][ty * 4];
            *(float4*)&b[0]  = *(const float4*)&Bs[cur][kk][tx * 8];
            *(float4*)&b[4]  = *(const float4*)&Bs[cur][kk][tx * 8 + 4];
            #pragma unroll
            for (int i = 0; i < 4; i++)
                #pragma unroll
                for (int j = 0; j < 8; j++)
                    acc[i][j] += a[i] * b[j];
        }
        if (k0 + 1 < nk) {
            int nxt = cur ^ 1;
            As[nxt][ac + 0][ar] = pa.x; As[nxt][ac + 1][ar] = pa.y;
            As[nxt][ac + 2][ar] = pa.z; As[nxt][ac + 3][ar] = pa.w;
            *(float4*)&Bs[nxt][br0][bc0] = pb0;
            *(float4*)&Bs[nxt][br1][bc0] = pb1;
        }
        __syncthreads();
    }
    #pragma unroll
    for (int i = 0; i < 4; i++) {
        float* cr = C + (size_t)(row0 + ty * 4 + i) * ldc + col0 + tx * 8;
        #pragma unroll
        for (int j = 0; j < 8; j += 4) {
            float4 v = make_float4(acc[i][j], acc[i][j + 1], acc[i][j + 2], acc[i][j + 3]);
            if (bias) {
                const float* bp = bias + col0 + tx * 8 + j;
                v.x += bp[0]; v.y += bp[1]; v.z += bp[2]; v.w += bp[3];
            }
            *(float4*)(cr + j) = v;
        }
    }
}

// ---------------------------------------------------------------------------
// NT variant for U: U[(r)*8+z][i] = sum_d Q[r, z*128+d] * Wk[i, z*128+d]
// A = Q (+z*128 col), B = Wk (row-major [i][1024], read transposed).
// grid (N/128, M/64, 8), K=128.
// ---------------------------------------------------------------------------
__global__ void __launch_bounds__(256) dbgemm_nt(
        const float* __restrict__ Q, const float* __restrict__ Wk,
        float* __restrict__ U) {
    int z = blockIdx.z;
    const float* A = Q + z * 128;           // lda = DM
    const float* B = Wk + z * 128;          // B[i][k] at B + i*DM + k
    float* C = U + (size_t)z * Ee;          // ldc = 8*Ee
    __shared__ float As[2][16][64];
    __shared__ float Bs[2][16][128];
    int tid = threadIdx.x;
    int row0 = blockIdx.y * 64, col0 = blockIdx.x * 128;
    int tx = tid & 15, ty = tid >> 4;
    int ar = tid >> 2, ac = (tid & 3) << 2;
    int bi0 = tid >> 2, bk0 = (tid & 3) << 2;    // first 64 i-rows
    int bi1 = bi0 + 64;
    float acc[4][8] = {};
    float4 pa, pb0, pb1;

    pa  = *(const float4*)(A + (size_t)(row0 + ar) * DM + ac);
    pb0 = *(const float4*)(B + (size_t)(col0 + bi0) * DM + bk0);
    pb1 = *(const float4*)(B + (size_t)(col0 + bi1) * DM + bk0);
    As[0][ac + 0][ar] = pa.x; As[0][ac + 1][ar] = pa.y;
    As[0][ac + 2][ar] = pa.z; As[0][ac + 3][ar] = pa.w;
    Bs[0][bk0 + 0][bi0] = pb0.x; Bs[0][bk0 + 1][bi0] = pb0.y;
    Bs[0][bk0 + 2][bi0] = pb0.z; Bs[0][bk0 + 3][bi0] = pb0.w;
    Bs[0][bk0 + 0][bi1] = pb1.x; Bs[0][bk0 + 1][bi1] = pb1.y;
    Bs[0][bk0 + 2][bi1] = pb1.z; Bs[0][bk0 + 3][bi1] = pb1.w;
    __syncthreads();

    const int nk = DEPTH >> 4;    // 8
    for (int k0 = 0; k0 < nk; k0++) {
        int cur = k0 & 1;
        if (k0 + 1 < nk) {
            int kb = (k0 + 1) << 4;
            pa  = *(const float4*)(A + (size_t)(row0 + ar) * DM + kb + ac);
            pb0 = *(const float4*)(B + (size_t)(col0 + bi0) * DM + kb + bk0);
            pb1 = *(const float4*)(B + (size_t)(col0 + bi1) * DM + kb + bk0);
        }
        #pragma unroll
        for (int kk = 0; kk < 16; kk++) {
            float a[4], b[8];
            *(float4*)a      = *(const float4*)&As[cur][kk][ty * 4];
            *(float4*)&b[0]  = *(const float4*)&Bs[cur][kk][tx * 8];
            *(float4*)&b[4]  = *(const float4*)&Bs[cur][kk][tx * 8 + 4];
            #pragma unroll
            for (int i = 0; i < 4; i++)
                #pragma unroll
                for (int j = 0; j < 8; j++)
                    acc[i][j] += a[i] * b[j];
        }
        if (k0 + 1 < nk) {
            int nxt = cur ^ 1;
            As[nxt][ac + 0][ar] = pa.x; As[nxt][ac + 1][ar] = pa.y;
            As[nxt][ac + 2][ar] = pa.z; As[nxt][ac + 3][ar] = pa.w;
            Bs[nxt][bk0 + 0][bi0] = pb0.x; Bs[nxt][bk0 + 1][bi0] = pb0.y;
            Bs[nxt][bk0 + 2][bi0] = pb0.z; Bs[nxt][bk0 + 3][bi0] = pb0.w;
            Bs[nxt][bk0 + 0][bi1] = pb1.x; Bs[nxt][bk0 + 1][bi1] = pb1.y;
            Bs[nxt][bk0 + 2][bi1] = pb1.z; Bs[nxt][bk0 + 3][bi1] = pb1.w;
        }
        __syncthreads();
    }
    #pragma unroll
    for (int i = 0; i < 4; i++) {
        float* cr = C + (size_t)(row0 + ty * 4 + i) * (8 * Ee) + col0 + tx * 8;
        #pragma unroll
        for (int j = 0; j < 8; j += 4)
            *(float4*)(cr + j) = make_float4(acc[i][j], acc[i][j + 1],
                                             acc[i][j + 2], acc[i][j + 3]);
    }
}

// ---------------------------------------------------------------------------
// Per-(bq,h) score constants via precomputed Rk/s1: one warp per (bq,h).
// ---------------------------------------------------------------------------
__global__ void __launch_bounds__(256) score_consts2(
        const float* __restrict__ Q, const float* __restrict__ Rk,
        const float* __restrict__ s1, float* __restrict__ r4, float* __restrict__ c0) {
    int warp = threadIdx.x >> 5, lane = threadIdx.x & 31;
    int i = blockIdx.x * 8 + warp;          // 0..8191
    int bq = i >> 3, h = i & 7;
    float4 qv = *(const float4*)(Q + (size_t)bq * DM + h * DEPTH + lane * 4);
    #pragma unroll
    for (int c = 0; c < 5; c++) {
        const float* src = (c < 4) ? (Rk + c * DM) : s1;
        float4 rv = *(const float4*)(src + h * DEPTH + lane * 4);
        float s = qv.x * rv.x + qv.y * rv.y + qv.z * rv.z + qv.w * rv.w;
        #pragma unroll
        for (int off = 16; off; off >>= 1) s += __shfl_xor_sync(0xffffffffu, s, off);
        if (lane == 0) {
            if (c < 4) r4[i * 4 + c] = s;
            else       c0[i] = s;
        }
    }
}

// ---------------------------------------------------------------------------
// Fused attention: scores (gather-dot) -> softmax -> xbar (gather-axpy).
// ---------------------------------------------------------------------------
#define ATTN_SMEM (13736 * 4)

__global__ void __launch_bounds__(256) attn_fused(
        const int* __restrict__ nt, const float* __restrict__ npos,
        const float* __restrict__ U, const float* __restrict__ r4,
        const float* __restrict__ c0, const float* __restrict__ text_table,
        float* __restrict__ xbar, float* __restrict__ wpos) {
    extern __shared__ float dyn[];
    float* sUt  = dyn;                  // [512][16] transposed u_top
    float* sT   = dyn + 8192;           // [100][33]
    float* sS   = dyn + 11492;          // [16][104]
    float* spos = dyn + 13156;          // [100][4]
    float* sr4  = dyn + 13556;          // [16][4]
    float* sc0  = dyn + 13620;          // [16]
    int*   sid  = (int*)(dyn + 13636);  // [100]

    int b = blockIdx.x, tid = threadIdx.x;
    int warp = tid >> 5, lane = tid & 31;

    for (int n = tid; n < Nn; n += 256) {
        int id = nt[b * Nn + n];
        sid[n] = id;
        float4 p = *(const float4*)(npos + (size_t)(b * Nn + n) * 4);
        spos[n * 4 + 0] = p.x; spos[n * 4 + 1] = p.y;
        spos[n * 4 + 2] = p.z; spos[n * 4 + 3] = p.w;
    }
    for (int idx = tid; idx < 16 * Ee; idx += 256) {
        int qh = idx >> 9, d = idx & 511;
        sUt[d * 16 + qh] = U[((size_t)b * 16 + qh) * Ee + d];
    }
    for (int idx = tid; idx < 64; idx += 256) sr4[idx] = r4[(size_t)b * 64 + idx];
    if (tid < 16) sc0[tid] = c0[(size_t)b * 16 + tid];
    __syncthreads();

    float m0 = (sid[0] == 0) ? 1.f : 0.f;
    float m1 = (sid[1] == 0) ? 1.f : 0.f;
    const float scale = 0.08838834764831845f;   // 1/sqrt(128)

    bool active = tid < 200;
    int qh0 = (tid & 7) * 2;
    int n0 = (tid >> 3) * 4;
    float acc[2][4] = {};

    for (int kc = 0; kc < 16; kc++) {
        for (int idx = tid; idx < Nn * 32; idx += 256) {
            int n = idx >> 5, d = idx & 31;
            sT[n * 33 + d] = text_table[(size_t)sid[n] * Ee + kc * 32 + d];
        }
        __syncthreads();
        if (active) {
            #pragma unroll
            for (int d = 0; d < 32; d++) {
                int gd = kc * 32 + d;
                float2 u2 = *(float2*)&sUt[gd * 16 + qh0];
                #pragma unroll
                for (int i = 0; i < 4; i++) {
                    float t = sT[(n0 + i) * 33 + d];
                    acc[0][i] += u2.x * t;
                    acc[1][i] += u2.y * t;
                }
            }
        }
        __syncthreads();
    }
    if (active) {
        #pragma unroll
        for (int j = 0; j < 2; j++) {
            int qh = qh0 + j;
            float mq = (qh < 8) ? m0 : m1;
            #pragma unroll
            for (int i = 0; i < 4; i++) {
                int n = n0 + i;
                float s = acc[j][i]
                        + spos[n * 4 + 0] * sr4[qh * 4 + 0]
                        + spos[n * 4 + 1] * sr4[qh * 4 + 1]
                        + spos[n * 4 + 2] * sr4[qh * 4 + 2]
                        + spos[n * 4 + 3] * sr4[qh * 4 + 3]
                        + sc0[qh];
                float mn = (sid[n] == 0) ? 1.f : 0.f;
                sS[qh * 104 + n] = s * scale + mq * mn * (-1e9f);
            }
        }
    }
    __syncthreads();

    for (int r = warp; r < 16; r += 8) {
        float* row = sS + r * 104;
        float mx = -1e30f;
        for (int jn = lane; jn < Nn; jn += 32) mx = fmaxf(mx, row[jn]);
        #pragma unroll
        for (int off = 16; off; off >>= 1)
            mx = fmaxf(mx, __shfl_xor_sync(0xffffffffu, mx, off));
        float ev[4]; int cnt = 0; float sum = 0.f;
        for (int jn = lane; jn < Nn; jn += 32) {
            float e = expf(row[jn] - mx);
            ev[cnt++] = e; sum += e;
        }
        #pragma unroll
        for (int off = 16; off; off >>= 1)
            sum += __shfl_xor_sync(0xffffffffu, sum, off);
        float inv = 1.f / sum;
        cnt = 0;
        for (int jn = lane; jn < Nn; jn += 32) row[jn] = ev[cnt++] * inv;
    }
    __syncthreads();

    if (tid < 64) {
        int qh = tid >> 2, c = tid & 3;
        float s = 0.f;
        for (int n = 0; n < Nn; n++) s += sS[qh * 104 + n] * spos[n * 4 + c];
        wpos[((size_t)b * 16 + qh) * 4 + c] = s;
    }

    float* sT2 = dyn;                   // reuse [16][512]
    int qh = tid & 15, dg = tid >> 4;
    float xa[32] = {};
    for (int nc = 0; nc < 7; nc++) {
        __syncthreads();
        for (int idx = tid; idx < 16 * Ee; idx += 256) {
            int rr = idx >> 9, d = idx & 511;
            int n = nc * 16 + rr;
            if (n < Nn) sT2[rr * Ee + d] = text_table[(size_t)sid[n] * Ee + d];
        }
        __syncthreads();
        int nmax = min(16, Nn - nc * 16);
        for (int rr = 0; rr < nmax; rr++) {
            float w = sS[qh * 104 + nc * 16 + rr];
            const float* tp = sT2 + rr * Ee + dg;
            #pragma unroll
            for (int j = 0; j < 32; j++) xa[j] += w * tp[16 * j];
        }
    }
    __syncthreads();
    float* sX = dyn;
    #pragma unroll
    for (int j = 0; j < 32; j++) sX[qh * Ee + dg + 16 * j] = xa[j];
    __syncthreads();
    for (int idx = tid; idx < 16 * Ee; idx += 256) {
        int q2 = idx >> 9, d = idx & 511;
        xbar[((size_t)b * 16 + q2) * Ee + d] = sX[idx];
    }
}

// ---------------------------------------------------------------------------
// att += wpos @ Mv + cv (elementwise epilogue, vectorized)
// ---------------------------------------------------------------------------
__global__ void att_post(float* __restrict__ att, const float* __restrict__ wpos,
                         const float* __restrict__ Mv, const float* __restrict__ cv) {
    int idx = blockIdx.x * blockDim.x + threadIdx.x;   // over 2^18 float4s
    if (idx >= 2 * Bsz * DM / 4) return;
    int r = idx >> 8;
    int c4 = (idx & 255) * 4;
    int z = c4 >> 7;
    const float* wp = wpos + ((size_t)r * 8 + z) * 4;
    float w0 = wp[0], w1 = wp[1], w2 = wp[2], w3 = wp[3];
    float4 v = *(float4*)(att + (size_t)r * DM + c4);
    #pragma unroll
    for (int u = 0; u < 4; u++) {
        int c = c4 + u;
        (&v.x)[u] += cv[c] + w0 * Mv[c] + w1 * Mv[DM + c]
                   + w2 * Mv[2 * DM + c] + w3 * Mv[3 * DM + c];
    }
    *(float4*)(att + (size_t)r * DM + c4) = v;
}

// ---------------------------------------------------------------------------
__global__ void pool_kernel(const float* __restrict__ O, float* __restrict__ pooled) {
    int idx = blockIdx.x * blockDim.x + threadIdx.x;
    if (idx >= Bsz * DM) return;
    int b = idx >> 10, k = idx & (DM - 1);
    pooled[idx] = fmaxf(O[(size_t)(2 * b) * DM + k], O[(size_t)(2 * b + 1) * DM + k]);
}

// ---------------------------------------------------------------------------
__global__ void __launch_bounds__(128) cosine_kernel(
        const float* __restrict__ enc, const float* __restrict__ cand_pos,
        const float* __restrict__ Mc, const int* __restrict__ field_id,
        const float* __restrict__ field_table, float* __restrict__ out) {
    __shared__ float red[3][4];
    int b = blockIdx.x, t = threadIdx.x;
    int warp = t >> 5, lane = t & 31;
    const float* fp = field_table + (size_t)field_id[b] * Ee;
    float4 cp = *(const float4*)(cand_pos + (size_t)b * 4);
    float na = 0.f, nb = 0.f, dp = 0.f;
    for (int j = t; j < Ee; j += 128) {
        float e = enc[(size_t)b * Ee + j]
                + cp.x * Mc[j] + cp.y * Mc[Ee + j]
                + cp.z * Mc[2 * Ee + j] + cp.w * Mc[3 * Ee + j];
        float f = fp[j];
        na += e * e; nb += f * f; dp += e * f;
    }
    #pragma unroll
    for (int off = 16; off; off >>= 1) {
        na += __shfl_xor_sync(0xffffffffu, na, off);
        nb += __shfl_xor_sync(0xffffffffu, nb, off);
        dp += __shfl_xor_sync(0xffffffffu, dp, off);
    }
    if (lane == 0) { red[0][warp] = na; red[1][warp] = nb; red[2][warp] = dp; }
    __syncthreads();
    if (t == 0) {
        na = red[0][0] + red[0][1] + red[0][2] + red[0][3];
        nb = red[1][0] + red[1][1] + red[1][2] + red[1][3];
        dp = red[2][0] + red[2][1] + red[2][2] + red[2][3];
        out[b] = -dp * rsqrtf(fmaxf(na, 1e-12f)) * rsqrtf(fmaxf(nb, 1e-12f));
    }
}

// ---------------------------------------------------------------------------
extern "C" void kernel_launch(void* const* d_in, const int* in_sizes, int n_in,
                              void* d_out, int out_size) {
    const int*   field_id   = (const int*)  d_in[0];
    const float* cand_pos   = (const float*)d_in[1];
    const int*   nt         = (const int*)  d_in[2];
    const float* npos       = (const float*)d_in[3];
    const float* text_table = (const float*)d_in[4];
    const float* field_tab  = (const float*)d_in[5];
    const float* cand_W     = (const float*)d_in[6];
    const float* cand_b     = (const float*)d_in[7];
    const float* pos_W      = (const float*)d_in[8];
    const float* pos_b      = (const float*)d_in[9];
    const float* Wq         = (const float*)d_in[10];
    const float* bq         = (const float*)d_in[11];
    const float* Wk         = (const float*)d_in[12];
    const float* bk         = (const float*)d_in[13];
    const float* Wv         = (const float*)d_in[14];
    const float* bv         = (const float*)d_in[15];
    const float* Wo         = (const float*)d_in[16];
    const float* bo         = (const float*)d_in[17];
    const float* proj_W     = (const float*)d_in[18];
    const float* proj_b     = (const float*)d_in[19];
    float* out = (float*)d_out;

    float *Xq, *Qb, *Ub, *r4b, *c0b, *xbarb, *wposb, *attb, *Ob, *poolb, *encb;
    float *Mvp, *cvp, *Mcp, *ccp, *Rkp, *s1p;
    cudaGetSymbolAddress((void**)&Xq,    g_Xq);
    cudaGetSymbolAddress((void**)&Qb,    g_Q);
    cudaGetSymbolAddress((void**)&Ub,    g_U);
    cudaGetSymbolAddress((void**)&r4b,   g_r4);
    cudaGetSymbolAddress((void**)&c0b,   g_c0);
    cudaGetSymbolAddress((void**)&xbarb, g_xbar);
    cudaGetSymbolAddress((void**)&wposb, g_wpos);
    cudaGetSymbolAddress((void**)&attb,  g_att);
    cudaGetSymbolAddress((void**)&Ob,    g_O);
    cudaGetSymbolAddress((void**)&poolb, g_pool);
    cudaGetSymbolAddress((void**)&encb,  g_enc);
    cudaGetSymbolAddress((void**)&Mvp,   g_Mv);
    cudaGetSymbolAddress((void**)&cvp,   g_cv);
    cudaGetSymbolAddress((void**)&Mcp,   g_Mc);
    cudaGetSymbolAddress((void**)&ccp,   g_cc);
    cudaGetSymbolAddress((void**)&Rkp,   g_Rk);
    cudaGetSymbolAddress((void**)&s1p,   g_s1);

    cudaFuncSetAttribute(attn_fused,
                         cudaFuncAttributeMaxDynamicSharedMemorySize, ATTN_SMEM);

    // rank-4 folds
    fuse_small<<<4, 256>>>(pos_W, pos_b, Wv + (size_t)Ee * DM, bv, Mvp, cvp, Ee, DM, DM);
    fuse_small<<<2, 256>>>(cand_W, cand_b, proj_W, proj_b, Mcp, ccp, Ee, Ee, Ee);
    fuse_small<<<4, 256>>>(pos_W, pos_b, Wk + (size_t)Ee * DM, bk, Rkp, s1p, Ee, DM, DM);

    // query inputs (rows 0,1 only)
    build_xq<<<2 * Bsz, 256>>>(nt, npos, text_table, pos_W, pos_b, Xq);

    // Q = Xq @ Wq + bq  (1024 x 1024 x 1024)
    dbgemm<<<dim3(8, 16, 1), 256>>>(Xq, DM, 0, Wq, DM, 0, Qb, DM, 0, bq, DM);

    // U_top[(bq)*8+h][i<512] = Wk_top_h @ q_h  (8 x [1024 x 512 x 128] NT)
    dbgemm_nt<<<dim3(4, 16, 8), 256>>>(Qb, Wk, Ub);

    // per-(bq,h) score constants from Rk/s1
    score_consts2<<<16 * Bsz / 8, 256>>>(Qb, Rkp, s1p, r4b, c0b);

    // fused gather-scores -> softmax -> xbar/wpos
    attn_fused<<<Bsz, 256, ATTN_SMEM>>>(nt, npos, Ub, r4b, c0b, text_table,
                                        xbarb, wposb);

    // att = xbar @ Wv_top  (8 x [1024 x 128 x 512], batched via z)
    dbgemm<<<dim3(1, 16, 8), 256>>>(xbarb, 8 * Ee, Ee, Wv, DM, 128,
                                    attb, DM, 128, nullptr, Ee);
    // att += wpos @ Mv + cv
    att_post<<<(2 * Bsz * DM / 4 + 255) / 256, 256>>>(attb, wposb, Mvp, cvp);

    // O = att @ Wo + bo
    dbgemm<<<dim3(8, 16, 1), 256>>>(attb, DM, 0, Wo, DM, 0, Ob, DM, 0, bo, DM);

    // pooled = max(O[2b], O[2b+1])
    pool_kernel<<<(Bsz * DM + 255) / 256, 256>>>(Ob, poolb);

    // enc = pooled @ proj_W[512:,:] + cc  (512 x 512 x 1024)
    dbgemm<<<dim3(4, 8, 1), 256>>>(poolb, DM, 0, proj_W + (size_t)Ee * Ee, Ee, 0,
                                   encb, Ee, 0, ccp, DM);

    // cosine loss
    cosine_kernel<<<Bsz, 128>>>(encb, cand_pos, Mcp, field_id, field_tab, out);
}